// round 5
// baseline (speedup 1.0000x reference)
#include <cuda_runtime.h>

#define NMAX 100000
#define EMAX 1600000
#define ODIM 32
#define KDIM 256
#define ALPHAF 0.2f

// ---------------- scratch (static device globals; no allocation) -------------
__device__ float  g_h[NMAX * ODIM];
__device__ float  g_zA[NMAX * ODIM];   // y ping
__device__ float  g_zB[NMAX * ODIM];   // y pong
__device__ int    g_cnt[NMAX];
__device__ float  g_dinv[NMAX];
__device__ float  g_a1[NMAX];          // 0.8 * dinv
__device__ int    g_ptr[NMAX + 1];
__device__ int    g_cursor[NMAX];
__device__ int    g_idx[EMAX + 8];     // source index per CSR slot
__device__ int    g_bsum[64];
__device__ int    g_boffs[64];

// ---------------- preprocessing kernels --------------------------------------

__global__ void zero_cnt_kernel(int n) {
    int i = blockIdx.x * blockDim.x + threadIdx.x;
    if (i < n) g_cnt[i] = 0;
}

// edge_index is INT32 on the wire.
__global__ void count_kernel(const int* __restrict__ ei, int E) {
    int e = blockIdx.x * blockDim.x + threadIdx.x;
    if (e < E) atomicAdd(&g_cnt[ei[E + e]], 1);
}

// --- blocksum + dinv fused (both read g_cnt) ---
__global__ void blocksum_kernel(int n) {
    int base = blockIdx.x * 4096;
    int tid = threadIdx.x;
    int s = 0;
#pragma unroll
    for (int i = 0; i < 8; ++i) {
        int idx = base + tid * 8 + i;
        if (idx < n) {
            int c = g_cnt[idx];
            s += c;
            float d = rsqrtf((float)(c + 1));   // +1 self-loop
            g_dinv[idx] = d;
            g_a1[idx] = (1.0f - ALPHAF) * d;
        }
    }
#pragma unroll
    for (int off = 16; off > 0; off >>= 1)
        s += __shfl_down_sync(0xffffffffu, s, off);
    __shared__ int wsums[16];
    int lane = tid & 31, wid = tid >> 5;
    if (lane == 0) wsums[wid] = s;
    __syncthreads();
    if (wid == 0) {
        int v = (lane < 16) ? wsums[lane] : 0;
#pragma unroll
        for (int off = 16; off > 0; off >>= 1)
            v += __shfl_down_sync(0xffffffffu, v, off);
        if (lane == 0) g_bsum[blockIdx.x] = v;
    }
}

__global__ void scan_bsums_kernel(int nb, int n) {
    int lane = threadIdx.x;
    int carry = 0;
    for (int base = 0; base < nb; base += 32) {
        int v = (base + lane < nb) ? g_bsum[base + lane] : 0;
        int inc = v;
#pragma unroll
        for (int off = 1; off < 32; off <<= 1) {
            int t = __shfl_up_sync(0xffffffffu, inc, off);
            if (lane >= off) inc += t;
        }
        if (base + lane < nb) g_boffs[base + lane] = carry + inc - v;
        carry += __shfl_sync(0xffffffffu, inc, 31);
    }
    if (lane == 0) g_ptr[n] = carry;
}

__global__ void scan_write_kernel(int n) {
    int base = blockIdx.x * 4096;
    int tid = threadIdx.x;
    int idx0 = base + tid * 8;
    int v[8], loc[8];
    int run = 0;
#pragma unroll
    for (int i = 0; i < 8; ++i) {
        v[i] = (idx0 + i < n) ? g_cnt[idx0 + i] : 0;
        loc[i] = run;
        run += v[i];
    }
    int lane = tid & 31, wid = tid >> 5;
    int incl = run;
#pragma unroll
    for (int off = 1; off < 32; off <<= 1) {
        int t = __shfl_up_sync(0xffffffffu, incl, off);
        if (lane >= off) incl += t;
    }
    __shared__ int wsums[16];
    if (lane == 31) wsums[wid] = incl;
    __syncthreads();
    if (wid == 0) {
        int x = (lane < 16) ? wsums[lane] : 0;
        int inc = x;
#pragma unroll
        for (int off = 1; off < 32; off <<= 1) {
            int t = __shfl_up_sync(0xffffffffu, inc, off);
            if (lane >= off) inc += t;
        }
        if (lane < 16) wsums[lane] = inc - x;  // exclusive warp offset
    }
    __syncthreads();
    int offset = g_boffs[blockIdx.x] + wsums[wid] + (incl - run);
#pragma unroll
    for (int i = 0; i < 8; ++i)
        if (idx0 + i < n) {
            g_ptr[idx0 + i] = offset + loc[i];
            g_cursor[idx0 + i] = offset + loc[i];
        }
}

__global__ void fill_kernel(const int* __restrict__ ei, int E) {
    int e = blockIdx.x * blockDim.x + threadIdx.x;
    if (e < E) {
        int r = ei[e];
        int c = ei[E + e];
        int pos = atomicAdd(&g_cursor[c], 1);
        g_idx[pos] = r;
    }
}

// ---------------- GEMM: h = x @ W^T + b; also y0 = dinv*h --------------------
__global__ __launch_bounds__(128) void gemm_kernel(
    const float* __restrict__ x, const float* __restrict__ W,
    const float* __restrict__ b, int n) {
    __shared__ float4 xs4[32][18];
    __shared__ float4 ws4[32][9];
    float* xsf = (float*)xs4;   // row stride 72 floats
    float* wsf = (float*)ws4;   // row stride 36 floats
    int tid = threadIdx.x;
    int tx = tid & 15;
    int ty = tid >> 4;
    int node0 = blockIdx.x * 64;
    const float4* x4 = (const float4*)x;
    const float4* W4 = (const float4*)W;
    float acc[4][4];
#pragma unroll
    for (int m = 0; m < 4; ++m)
#pragma unroll
        for (int o = 0; o < 4; ++o) acc[m][o] = 0.0f;

    for (int kt = 0; kt < KDIM; kt += 32) {
        int kt4 = kt >> 2;
#pragma unroll
        for (int i = 0; i < 4; ++i) {
            int f = tid + i * 128;
            int row = f >> 3, kq = f & 7;
            float4 v = make_float4(0.f, 0.f, 0.f, 0.f);
            if (node0 + row < n) v = x4[(size_t)(node0 + row) * 64 + kt4 + kq];
            xsf[(kq * 4 + 0) * 72 + row] = v.x;
            xsf[(kq * 4 + 1) * 72 + row] = v.y;
            xsf[(kq * 4 + 2) * 72 + row] = v.z;
            xsf[(kq * 4 + 3) * 72 + row] = v.w;
        }
#pragma unroll
        for (int i = 0; i < 2; ++i) {
            int f = tid + i * 128;
            int j = f >> 3, kq = f & 7;
            float4 v = W4[j * 64 + kt4 + kq];
            wsf[(kq * 4 + 0) * 36 + j] = v.x;
            wsf[(kq * 4 + 1) * 36 + j] = v.y;
            wsf[(kq * 4 + 2) * 36 + j] = v.z;
            wsf[(kq * 4 + 3) * 36 + j] = v.w;
        }
        __syncthreads();
#pragma unroll
        for (int k = 0; k < 32; ++k) {
            float4 xv = xs4[k][tx];
            float4 wv = ws4[k][ty];
            float xm[4] = {xv.x, xv.y, xv.z, xv.w};
            float wm[4] = {wv.x, wv.y, wv.z, wv.w};
#pragma unroll
            for (int m = 0; m < 4; ++m)
#pragma unroll
                for (int o = 0; o < 4; ++o)
                    acc[m][o] = fmaf(xm[m], wm[o], acc[m][o]);
        }
        __syncthreads();
    }
#pragma unroll
    for (int m = 0; m < 4; ++m) {
        int node = node0 + tx * 4 + m;
        if (node < n) {
            float d = g_dinv[node];
#pragma unroll
            for (int o = 0; o < 4; ++o) {
                float hv = acc[m][o] + b[ty * 4 + o];
                g_h[(size_t)node * ODIM + ty * 4 + o] = hv;
                g_zA[(size_t)node * ODIM + ty * 4 + o] = d * hv;  // y0
            }
        }
    }
}

// ---------------- propagation: warp/node, pipelined idx prefetch -------------
__global__ __launch_bounds__(512) void prop_kernel(
    const float* __restrict__ prelu_a, float* __restrict__ out,
    int n, int it) {
    const float* yin = (it & 1) ? g_zA : g_zB;   // it=1 reads y0 in zA
    int fin = (it == 10);
    float* yout = (it & 1) ? g_zB : g_zA;

    int node = blockIdx.x * 16 + (threadIdx.x >> 5);
    if (node >= n) return;
    int lane = threadIdx.x & 31;
    int grp = lane >> 3;   // edge group 0..3
    int f4 = lane & 7;     // float4 slot within row

    int s = g_ptr[node];
    int e = g_ptr[node + 1];
    const float4* y4 = (const float4*)yin;

    // hoist epilogue loads so they overlap the gather chain
    float4 selfv = make_float4(0.f, 0.f, 0.f, 0.f);
    float4 hv = make_float4(0.f, 0.f, 0.f, 0.f);
    if (lane < 8) {
        selfv = y4[(size_t)node * 8 + lane];
        hv = ((const float4*)g_h)[(size_t)node * 8 + lane];
    }
    float a1 = g_a1[node];
    float d = g_dinv[node];

    float4 acc = make_float4(0.f, 0.f, 0.f, 0.f);
    int i = s;
    // pipelined main loop: 8 edges/round, next round's idx prefetched
    int nidx0 = 0, nidx1 = 0;
    bool have = (i + 8 <= e);
    if (have) {
        nidx0 = g_idx[i + grp];
        nidx1 = g_idx[i + 4 + grp];
    }
    while (have) {
        int c0 = nidx0, c1 = nidx1;
        i += 8;
        have = (i + 8 <= e);
        if (have) {
            nidx0 = g_idx[i + grp];
            nidx1 = g_idx[i + 4 + grp];
        }
        float4 v0 = y4[(size_t)c0 * 8 + f4];
        float4 v1 = y4[(size_t)c1 * 8 + f4];
        acc.x += v0.x + v1.x;
        acc.y += v0.y + v1.y;
        acc.z += v0.z + v1.z;
        acc.w += v0.w + v1.w;
    }
    if (i + 4 <= e) {
        int c0 = g_idx[i + grp];
        float4 v0 = y4[(size_t)c0 * 8 + f4];
        acc.x += v0.x; acc.y += v0.y; acc.z += v0.z; acc.w += v0.w;
        i += 4;
    }
    // reduce the 4 edge-groups onto lanes 0..7
    acc.x += __shfl_xor_sync(0xffffffffu, acc.x, 8);
    acc.y += __shfl_xor_sync(0xffffffffu, acc.y, 8);
    acc.z += __shfl_xor_sync(0xffffffffu, acc.z, 8);
    acc.w += __shfl_xor_sync(0xffffffffu, acc.w, 8);
    acc.x += __shfl_xor_sync(0xffffffffu, acc.x, 16);
    acc.y += __shfl_xor_sync(0xffffffffu, acc.y, 16);
    acc.z += __shfl_xor_sync(0xffffffffu, acc.z, 16);
    acc.w += __shfl_xor_sync(0xffffffffu, acc.w, 16);
    // remainder (<=3 edges): lanes 0..7 gather full rows
    for (; i < e; ++i) {
        int idx = g_idx[i];
        if (lane < 8) {
            float4 v = y4[(size_t)idx * 8 + lane];
            acc.x += v.x; acc.y += v.y; acc.z += v.z; acc.w += v.w;
        }
    }
    if (lane < 8) {
        acc.x += selfv.x; acc.y += selfv.y; acc.z += selfv.z; acc.w += selfv.w;
        float4 z;
        z.x = fmaf(a1, acc.x, ALPHAF * hv.x);
        z.y = fmaf(a1, acc.y, ALPHAF * hv.y);
        z.z = fmaf(a1, acc.z, ALPHAF * hv.z);
        z.w = fmaf(a1, acc.w, ALPHAF * hv.w);
        if (fin) {
            float4 pa = ((const float4*)prelu_a)[lane];
            z.x = (z.x >= 0.f) ? z.x : pa.x * z.x;
            z.y = (z.y >= 0.f) ? z.y : pa.y * z.y;
            z.z = (z.z >= 0.f) ? z.z : pa.z * z.z;
            z.w = (z.w >= 0.f) ? z.w : pa.w * z.w;
            ((float4*)out)[(size_t)node * 8 + lane] = z;
        } else {
            z.x *= d; z.y *= d; z.z *= d; z.w *= d;
            ((float4*)yout)[(size_t)node * 8 + lane] = z;
        }
    }
}

// ---------------- launch ------------------------------------------------------
extern "C" void kernel_launch(void* const* d_in, const int* in_sizes, int n_in,
                              void* d_out, int out_size) {
    const float* x = (const float*)d_in[0];
    const int* ei = (const int*)d_in[1];   // int32 edge_index [2, E]
    const float* W = (const float*)d_in[2];
    const float* b = (const float*)d_in[3];
    const float* pa = (const float*)d_in[4];

    int n = in_sizes[0] / KDIM;
    int E = in_sizes[1] / 2;
    int nb = (n + 4095) / 4096;

    zero_cnt_kernel<<<(n + 255) / 256, 256>>>(n);
    count_kernel<<<(E + 255) / 256, 256>>>(ei, E);
    blocksum_kernel<<<nb, 512>>>(n);          // fused dinv/a1
    scan_bsums_kernel<<<1, 32>>>(nb, n);
    scan_write_kernel<<<nb, 512>>>(n);
    fill_kernel<<<(E + 255) / 256, 256>>>(ei, E);

    gemm_kernel<<<(n + 63) / 64, 128>>>(x, W, b, n);

    for (int it = 1; it <= 10; ++it)
        prop_kernel<<<(n + 15) / 16, 512>>>(pa, (float*)d_out, n, it);
}

// round 6
// speedup vs baseline: 1.3959x; 1.3959x over previous
#include <cuda_runtime.h>

#define NMAX 100000
#define EMAX 1600000
#define ODIM 32
#define KDIM 256
#define ALPHAF 0.2f

// ---------------- scratch (static device globals; no allocation) -------------
__device__ float  g_h[NMAX * ODIM];
__device__ float  g_zA[NMAX * ODIM];   // y ping
__device__ float  g_zB[NMAX * ODIM];   // y pong
__device__ int    g_cnt[NMAX];
__device__ float  g_dinv[NMAX];
__device__ float  g_a1[NMAX];          // 0.8 * dinv
__device__ int    g_ptr[NMAX + 1];
__device__ int    g_cursor[NMAX];
__device__ int    g_idx[EMAX + 16];    // source index per CSR slot
__device__ int    g_bsum[64];
__device__ int    g_boffs[64];

// ---------------- preprocessing kernels --------------------------------------

__global__ void zero_cnt_kernel(int n) {
    int i = blockIdx.x * blockDim.x + threadIdx.x;
    if (i < n) g_cnt[i] = 0;
}

// edge_index is INT32 on the wire.
__global__ void count_kernel(const int* __restrict__ ei, int E) {
    int e = blockIdx.x * blockDim.x + threadIdx.x;
    if (e < E) atomicAdd(&g_cnt[ei[E + e]], 1);
}

// --- blocksum + dinv fused (both read g_cnt) ---
__global__ void blocksum_kernel(int n) {
    int base = blockIdx.x * 4096;
    int tid = threadIdx.x;
    int s = 0;
#pragma unroll
    for (int i = 0; i < 8; ++i) {
        int idx = base + tid * 8 + i;
        if (idx < n) {
            int c = g_cnt[idx];
            s += c;
            float d = rsqrtf((float)(c + 1));   // +1 self-loop
            g_dinv[idx] = d;
            g_a1[idx] = (1.0f - ALPHAF) * d;
        }
    }
#pragma unroll
    for (int off = 16; off > 0; off >>= 1)
        s += __shfl_down_sync(0xffffffffu, s, off);
    __shared__ int wsums[16];
    int lane = tid & 31, wid = tid >> 5;
    if (lane == 0) wsums[wid] = s;
    __syncthreads();
    if (wid == 0) {
        int v = (lane < 16) ? wsums[lane] : 0;
#pragma unroll
        for (int off = 16; off > 0; off >>= 1)
            v += __shfl_down_sync(0xffffffffu, v, off);
        if (lane == 0) g_bsum[blockIdx.x] = v;
    }
}

__global__ void scan_bsums_kernel(int nb, int n) {
    int lane = threadIdx.x;
    int carry = 0;
    for (int base = 0; base < nb; base += 32) {
        int v = (base + lane < nb) ? g_bsum[base + lane] : 0;
        int inc = v;
#pragma unroll
        for (int off = 1; off < 32; off <<= 1) {
            int t = __shfl_up_sync(0xffffffffu, inc, off);
            if (lane >= off) inc += t;
        }
        if (base + lane < nb) g_boffs[base + lane] = carry + inc - v;
        carry += __shfl_sync(0xffffffffu, inc, 31);
    }
    if (lane == 0) g_ptr[n] = carry;
}

__global__ void scan_write_kernel(int n) {
    int base = blockIdx.x * 4096;
    int tid = threadIdx.x;
    int idx0 = base + tid * 8;
    int v[8], loc[8];
    int run = 0;
#pragma unroll
    for (int i = 0; i < 8; ++i) {
        v[i] = (idx0 + i < n) ? g_cnt[idx0 + i] : 0;
        loc[i] = run;
        run += v[i];
    }
    int lane = tid & 31, wid = tid >> 5;
    int incl = run;
#pragma unroll
    for (int off = 1; off < 32; off <<= 1) {
        int t = __shfl_up_sync(0xffffffffu, incl, off);
        if (lane >= off) incl += t;
    }
    __shared__ int wsums[16];
    if (lane == 31) wsums[wid] = incl;
    __syncthreads();
    if (wid == 0) {
        int x = (lane < 16) ? wsums[lane] : 0;
        int inc = x;
#pragma unroll
        for (int off = 1; off < 32; off <<= 1) {
            int t = __shfl_up_sync(0xffffffffu, inc, off);
            if (lane >= off) inc += t;
        }
        if (lane < 16) wsums[lane] = inc - x;  // exclusive warp offset
    }
    __syncthreads();
    int offset = g_boffs[blockIdx.x] + wsums[wid] + (incl - run);
#pragma unroll
    for (int i = 0; i < 8; ++i)
        if (idx0 + i < n) {
            g_ptr[idx0 + i] = offset + loc[i];
            g_cursor[idx0 + i] = offset + loc[i];
        }
}

__global__ void fill_kernel(const int* __restrict__ ei, int E) {
    int e = blockIdx.x * blockDim.x + threadIdx.x;
    if (e < E) {
        int r = ei[e];
        int c = ei[E + e];
        int pos = atomicAdd(&g_cursor[c], 1);
        g_idx[pos] = r;
    }
}

// ---------------- GEMM: h = x @ W^T + b; also y0 = dinv*h --------------------
__global__ __launch_bounds__(128) void gemm_kernel(
    const float* __restrict__ x, const float* __restrict__ W,
    const float* __restrict__ b, int n) {
    __shared__ float4 xs4[32][18];
    __shared__ float4 ws4[32][9];
    float* xsf = (float*)xs4;   // row stride 72 floats
    float* wsf = (float*)ws4;   // row stride 36 floats
    int tid = threadIdx.x;
    int tx = tid & 15;
    int ty = tid >> 4;
    int node0 = blockIdx.x * 64;
    const float4* x4 = (const float4*)x;
    const float4* W4 = (const float4*)W;
    float acc[4][4];
#pragma unroll
    for (int m = 0; m < 4; ++m)
#pragma unroll
        for (int o = 0; o < 4; ++o) acc[m][o] = 0.0f;

    for (int kt = 0; kt < KDIM; kt += 32) {
        int kt4 = kt >> 2;
#pragma unroll
        for (int i = 0; i < 4; ++i) {
            int f = tid + i * 128;
            int row = f >> 3, kq = f & 7;
            float4 v = make_float4(0.f, 0.f, 0.f, 0.f);
            if (node0 + row < n) v = x4[(size_t)(node0 + row) * 64 + kt4 + kq];
            xsf[(kq * 4 + 0) * 72 + row] = v.x;
            xsf[(kq * 4 + 1) * 72 + row] = v.y;
            xsf[(kq * 4 + 2) * 72 + row] = v.z;
            xsf[(kq * 4 + 3) * 72 + row] = v.w;
        }
#pragma unroll
        for (int i = 0; i < 2; ++i) {
            int f = tid + i * 128;
            int j = f >> 3, kq = f & 7;
            float4 v = W4[j * 64 + kt4 + kq];
            wsf[(kq * 4 + 0) * 36 + j] = v.x;
            wsf[(kq * 4 + 1) * 36 + j] = v.y;
            wsf[(kq * 4 + 2) * 36 + j] = v.z;
            wsf[(kq * 4 + 3) * 36 + j] = v.w;
        }
        __syncthreads();
#pragma unroll
        for (int k = 0; k < 32; ++k) {
            float4 xv = xs4[k][tx];
            float4 wv = ws4[k][ty];
            float xm[4] = {xv.x, xv.y, xv.z, xv.w};
            float wm[4] = {wv.x, wv.y, wv.z, wv.w};
#pragma unroll
            for (int m = 0; m < 4; ++m)
#pragma unroll
                for (int o = 0; o < 4; ++o)
                    acc[m][o] = fmaf(xm[m], wm[o], acc[m][o]);
        }
        __syncthreads();
    }
#pragma unroll
    for (int m = 0; m < 4; ++m) {
        int node = node0 + tx * 4 + m;
        if (node < n) {
            float d = g_dinv[node];
#pragma unroll
            for (int o = 0; o < 4; ++o) {
                float hv = acc[m][o] + b[ty * 4 + o];
                g_h[(size_t)node * ODIM + ty * 4 + o] = hv;
                g_zA[(size_t)node * ODIM + ty * 4 + o] = d * hv;  // y0
            }
        }
    }
}

// ---------------- propagation: warp per node, 16 edges/round -----------------
__global__ __launch_bounds__(256) void prop_kernel(
    const float* __restrict__ prelu_a, float* __restrict__ out,
    int n, int it) {
    const float* yin = (it & 1) ? g_zA : g_zB;   // it=1 reads y0 in zA
    int fin = (it == 10);
    float* yout = (it & 1) ? g_zB : g_zA;

    int node = blockIdx.x * 8 + (threadIdx.x >> 5);
    if (node >= n) return;
    int lane = threadIdx.x & 31;
    int grp = lane >> 3;   // edge group 0..3
    int f4 = lane & 7;     // float4 slot within row

    int s = g_ptr[node];
    int e = g_ptr[node + 1];
    const float4* y4 = (const float4*)yin;

    float4 acc = make_float4(0.f, 0.f, 0.f, 0.f);
    int i = s;
    // 16 edges per round: 4 independent idx loads + 4 independent gathers
    for (; i + 16 <= e; i += 16) {
        int i0 = g_idx[i + grp];
        int i1 = g_idx[i + 4 + grp];
        int i2 = g_idx[i + 8 + grp];
        int i3 = g_idx[i + 12 + grp];
        float4 v0 = y4[(size_t)i0 * 8 + f4];
        float4 v1 = y4[(size_t)i1 * 8 + f4];
        float4 v2 = y4[(size_t)i2 * 8 + f4];
        float4 v3 = y4[(size_t)i3 * 8 + f4];
        acc.x += (v0.x + v1.x) + (v2.x + v3.x);
        acc.y += (v0.y + v1.y) + (v2.y + v3.y);
        acc.z += (v0.z + v1.z) + (v2.z + v3.z);
        acc.w += (v0.w + v1.w) + (v2.w + v3.w);
    }
    if (i + 8 <= e) {
        int i0 = g_idx[i + grp];
        int i1 = g_idx[i + 4 + grp];
        float4 v0 = y4[(size_t)i0 * 8 + f4];
        float4 v1 = y4[(size_t)i1 * 8 + f4];
        acc.x += v0.x + v1.x;
        acc.y += v0.y + v1.y;
        acc.z += v0.z + v1.z;
        acc.w += v0.w + v1.w;
        i += 8;
    }
    if (i + 4 <= e) {
        int i0 = g_idx[i + grp];
        float4 v0 = y4[(size_t)i0 * 8 + f4];
        acc.x += v0.x; acc.y += v0.y; acc.z += v0.z; acc.w += v0.w;
        i += 4;
    }
    // reduce the 4 edge-groups onto lanes 0..7
    acc.x += __shfl_xor_sync(0xffffffffu, acc.x, 8);
    acc.y += __shfl_xor_sync(0xffffffffu, acc.y, 8);
    acc.z += __shfl_xor_sync(0xffffffffu, acc.z, 8);
    acc.w += __shfl_xor_sync(0xffffffffu, acc.w, 8);
    acc.x += __shfl_xor_sync(0xffffffffu, acc.x, 16);
    acc.y += __shfl_xor_sync(0xffffffffu, acc.y, 16);
    acc.z += __shfl_xor_sync(0xffffffffu, acc.z, 16);
    acc.w += __shfl_xor_sync(0xffffffffu, acc.w, 16);
    // remainder (<=3 edges): lanes 0..7 gather full rows
    for (; i < e; ++i) {
        int idx = g_idx[i];
        if (lane < 8) {
            float4 v = y4[(size_t)idx * 8 + lane];
            acc.x += v.x; acc.y += v.y; acc.z += v.z; acc.w += v.w;
        }
    }
    if (lane < 8) {
        float4 selfv = y4[(size_t)node * 8 + lane];    // self-loop: + y[c]
        acc.x += selfv.x; acc.y += selfv.y; acc.z += selfv.z; acc.w += selfv.w;
        float a1 = g_a1[node];
        float4 hv = ((const float4*)g_h)[(size_t)node * 8 + lane];
        float4 z;
        z.x = fmaf(a1, acc.x, ALPHAF * hv.x);
        z.y = fmaf(a1, acc.y, ALPHAF * hv.y);
        z.z = fmaf(a1, acc.z, ALPHAF * hv.z);
        z.w = fmaf(a1, acc.w, ALPHAF * hv.w);
        if (fin) {
            float4 pa = ((const float4*)prelu_a)[lane];
            z.x = (z.x >= 0.f) ? z.x : pa.x * z.x;
            z.y = (z.y >= 0.f) ? z.y : pa.y * z.y;
            z.z = (z.z >= 0.f) ? z.z : pa.z * z.z;
            z.w = (z.w >= 0.f) ? z.w : pa.w * z.w;
            ((float4*)out)[(size_t)node * 8 + lane] = z;
        } else {
            float d = g_dinv[node];
            z.x *= d; z.y *= d; z.z *= d; z.w *= d;
            ((float4*)yout)[(size_t)node * 8 + lane] = z;
        }
    }
}

// ---------------- launch ------------------------------------------------------
extern "C" void kernel_launch(void* const* d_in, const int* in_sizes, int n_in,
                              void* d_out, int out_size) {
    const float* x = (const float*)d_in[0];
    const int* ei = (const int*)d_in[1];   // int32 edge_index [2, E]
    const float* W = (const float*)d_in[2];
    const float* b = (const float*)d_in[3];
    const float* pa = (const float*)d_in[4];

    int n = in_sizes[0] / KDIM;
    int E = in_sizes[1] / 2;
    int nb = (n + 4095) / 4096;

    zero_cnt_kernel<<<(n + 255) / 256, 256>>>(n);
    count_kernel<<<(E + 255) / 256, 256>>>(ei, E);
    blocksum_kernel<<<nb, 512>>>(n);          // fused dinv/a1
    scan_bsums_kernel<<<1, 32>>>(nb, n);
    scan_write_kernel<<<nb, 512>>>(n);
    fill_kernel<<<(E + 255) / 256, 256>>>(ei, E);

    gemm_kernel<<<(n + 63) / 64, 128>>>(x, W, b, n);

    for (int it = 1; it <= 10; ++it)
        prop_kernel<<<(n + 7) / 8, 256>>>(pa, (float*)d_out, n, it);
}